// round 1
// baseline (speedup 1.0000x reference)
#include <cuda_runtime.h>
#include <math.h>

#define EPSV 1e-5f

// ---------------- scratch (allocation-free: device globals) ----------------
__device__ float g_ss  [64*1024];
__device__ float g_h   [64*512*512];
__device__ float g_h2  [64*512*512];
__device__ float g_xln [64*512*512];
__device__ float g_q   [64*512*512];
__device__ float g_cn  [64*768*77];
__device__ float g_k   [64*512*77];
__device__ float g_v   [64*512*77];
__device__ float g_attn[64*8*64*64];

__device__ __forceinline__ float mishf(float x){
    // x * tanh(log1p(exp(x))) , stable logaddexp(x,0)
    float sp = fmaxf(x, 0.f) + log1pf(expf(-fabsf(x)));
    return x * tanhf(sp);
}

// ---------------- ss = mish(t) @ tm_w^T + tm_b -----------------------------
__global__ void k_ss(const float* __restrict__ t, const float* __restrict__ w,
                     const float* __restrict__ bias){
    __shared__ float tm[512];
    int b = blockIdx.x, tid = threadIdx.x;
    for (int i = tid; i < 512; i += 256) tm[i] = mishf(t[b*512 + i]);
    __syncthreads();
    for (int o = tid; o < 1024; o += 256){
        const float* wr = w + (size_t)o * 512;
        float acc = bias[o];
        #pragma unroll 8
        for (int i = 0; i < 512; i++) acc = fmaf(tm[i], wr[i], acc);
        g_ss[b*1024 + o] = acc;
    }
}

// ---------------- generic conv1d (GEMM-style) -------------------------------
// out[b,co,l] = bias[co] + sum_{ci,k} w[co,ci,k] * in[b,ci,l+k-PAD]
// grid: (ceil(L/128), Cout/64, B), block 256. 4 co x 8 l per thread.
template<int CIN, int TAPS, int PAD>
__global__ void k_conv(const float* __restrict__ in, const float* __restrict__ w,
                       const float* __restrict__ bias, float* __restrict__ out, int L){
    constexpr int LW  = 128 + TAPS - 1;
    constexpr int NXR = 8 + TAPS - 1;
    __shared__ __align__(16) float xs[16][LW];
    __shared__ float ws[64][16][TAPS];
    const int l0  = blockIdx.x * 128;
    const int co0 = blockIdx.y * 64;
    const int b   = blockIdx.z;
    const int COUT = gridDim.y * 64;
    const int tid = threadIdx.x, tx = tid & 15, ty = tid >> 4;

    float acc[4][8];
    #pragma unroll
    for (int c = 0; c < 4; c++)
        #pragma unroll
        for (int j = 0; j < 8; j++) acc[c][j] = 0.f;

    const float* inb = in + (size_t)b * CIN * L;

    for (int ci0 = 0; ci0 < CIN; ci0 += 16){
        for (int idx = tid; idx < 16*LW; idx += 256){
            int r = idx / LW, cc = idx - r*LW;
            int l = l0 + cc - PAD;
            xs[r][cc] = (l >= 0 && l < L) ? inb[(size_t)(ci0 + r)*L + l] : 0.f;
        }
        for (int idx = tid; idx < 64*16*TAPS; idx += 256){
            int c = idx / (16*TAPS); int rem = idx - c*16*TAPS;
            int i = rem / TAPS;      int k = rem - i*TAPS;
            ws[c][i][k] = w[((size_t)(co0 + c)*CIN + ci0 + i)*TAPS + k];
        }
        __syncthreads();
        #pragma unroll
        for (int i = 0; i < 16; i++){
            float xr[NXR];
            #pragma unroll
            for (int v = 0; v < NXR/4; v++){
                float4 t4 = *reinterpret_cast<const float4*>(&xs[i][tx*8 + v*4]);
                xr[v*4+0] = t4.x; xr[v*4+1] = t4.y; xr[v*4+2] = t4.z; xr[v*4+3] = t4.w;
            }
            #pragma unroll
            for (int c = 0; c < 4; c++){
                #pragma unroll
                for (int k = 0; k < TAPS; k++){
                    float wv = ws[ty*4 + c][i][k];
                    #pragma unroll
                    for (int j = 0; j < 8; j++)
                        acc[c][j] = fmaf(wv, xr[j + k], acc[c][j]);
                }
            }
        }
        __syncthreads();
    }
    #pragma unroll
    for (int c = 0; c < 4; c++){
        int co = co0 + ty*4 + c;
        float bv = bias[co];
        #pragma unroll
        for (int j = 0; j < 8; j++){
            int l = l0 + tx*8 + j;
            if (l < L) out[((size_t)b*COUT + co)*L + l] = acc[c][j] + bv;
        }
    }
}

// ---------------- GN0 + FiLM + mish -----------------------------------------
// per (b, group, l): normalize 64 channels; grid (16 ltiles, 8 g, 64 b)
__global__ void k_gn0(const float* __restrict__ in, const float* __restrict__ gg,
                      const float* __restrict__ gb, float* __restrict__ out){
    __shared__ float tile[64][32];
    __shared__ float rs[8][32], rq[8][32];
    __shared__ float cm[32], cr[32];
    int l0 = blockIdx.x*32, g = blockIdx.y, b = blockIdx.z;
    int tid = threadIdx.x, col = tid & 31, seg = tid >> 5;
    size_t base = ((size_t)(b*512 + g*64))*512 + l0;
    #pragma unroll
    for (int k = 0; k < 8; k++){
        int idx = k*256 + tid; int r = idx >> 5, c = idx & 31;
        tile[r][c] = in[base + (size_t)r*512 + c];
    }
    __syncthreads();
    float s = 0.f, q = 0.f;
    #pragma unroll
    for (int r = 0; r < 8; r++){ float v = tile[seg*8 + r][col]; s += v; q += v*v; }
    rs[seg][col] = s; rq[seg][col] = q;
    __syncthreads();
    if (tid < 32){
        float S = 0.f, Q = 0.f;
        #pragma unroll
        for (int w = 0; w < 8; w++){ S += rs[w][tid]; Q += rq[w][tid]; }
        float m = S * (1.f/64.f); float var = Q * (1.f/64.f) - m*m;
        cm[tid] = m; cr[tid] = rsqrtf(var + EPSV);
    }
    __syncthreads();
    #pragma unroll
    for (int k = 0; k < 8; k++){
        int idx = k*256 + tid; int r = idx >> 5, c = idx & 31;
        int ch = g*64 + r;
        float v = (tile[r][c] - cm[c]) * cr[c] * gg[ch] + gb[ch];
        float sc = g_ss[b*1024 + ch], sh = g_ss[b*1024 + 512 + ch];
        v = v * (1.f + sc) + sh;
        out[base + (size_t)r*512 + c] = mishf(v);
    }
}

// ---------------- GN1 + mish + residual add (in-place on d_out) -------------
__global__ void k_gn1(const float* __restrict__ in, const float* __restrict__ gg,
                      const float* __restrict__ gb, float* __restrict__ dout){
    __shared__ float tile[64][32];
    __shared__ float rs[8][32], rq[8][32];
    __shared__ float cm[32], cr[32];
    int l0 = blockIdx.x*32, g = blockIdx.y, b = blockIdx.z;
    int tid = threadIdx.x, col = tid & 31, seg = tid >> 5;
    size_t base = ((size_t)(b*512 + g*64))*512 + l0;
    #pragma unroll
    for (int k = 0; k < 8; k++){
        int idx = k*256 + tid; int r = idx >> 5, c = idx & 31;
        tile[r][c] = in[base + (size_t)r*512 + c];
    }
    __syncthreads();
    float s = 0.f, q = 0.f;
    #pragma unroll
    for (int r = 0; r < 8; r++){ float v = tile[seg*8 + r][col]; s += v; q += v*v; }
    rs[seg][col] = s; rq[seg][col] = q;
    __syncthreads();
    if (tid < 32){
        float S = 0.f, Q = 0.f;
        #pragma unroll
        for (int w = 0; w < 8; w++){ S += rs[w][tid]; Q += rq[w][tid]; }
        float m = S * (1.f/64.f); float var = Q * (1.f/64.f) - m*m;
        cm[tid] = m; cr[tid] = rsqrtf(var + EPSV);
    }
    __syncthreads();
    #pragma unroll
    for (int k = 0; k < 8; k++){
        int idx = k*256 + tid; int r = idx >> 5, c = idx & 31;
        int ch = g*64 + r;
        float v = (tile[r][c] - cm[c]) * cr[c] * gg[ch] + gb[ch];
        size_t o = base + (size_t)r*512 + c;
        dout[o] = mishf(v) + dout[o];
    }
}

// ---------------- LN over channels of out[cidx[b]] -> g_xln (b,c,t) ---------
__global__ void k_xln(const float* __restrict__ out, const float* __restrict__ gg,
                      const float* __restrict__ gb, const int* __restrict__ cidx){
    int b = blockIdx.y;
    int t = blockIdx.x*128 + threadIdx.x;
    int bi = cidx[b];
    const float* src = out + (size_t)bi*512*512 + t;
    float s = 0.f, q = 0.f;
    for (int c = 0; c < 512; c++){ float v = src[(size_t)c*512]; s += v; q += v*v; }
    float m = s * (1.f/512.f);
    float r = rsqrtf(q * (1.f/512.f) - m*m + EPSV);
    float* dst = g_xln + (size_t)b*512*512 + t;
    for (int c = 0; c < 512; c++){
        float v = src[(size_t)c*512];
        dst[(size_t)c*512] = (v - m) * r * gg[c] + gb[c];
    }
}

// ---------------- LN(cond[cidx[b]]) -> g_cn (b, 768, 77) transposed ---------
__global__ void k_cn(const float* __restrict__ cond, const float* __restrict__ gg,
                     const float* __restrict__ gb, const int* __restrict__ cidx){
    __shared__ float row[768];
    __shared__ float wsum[8], wsq[8];
    int n = blockIdx.x, b = blockIdx.y;
    int bi = cidx[b];
    int tid = threadIdx.x, lane = tid & 31, w = tid >> 5;
    const float* src = cond + ((size_t)bi*77 + n)*768;
    float s = 0.f, q = 0.f;
    for (int i = tid; i < 768; i += 256){ float v = src[i]; row[i] = v; s += v; q += v*v; }
    #pragma unroll
    for (int o = 16; o; o >>= 1){ s += __shfl_xor_sync(0xffffffffu, s, o); q += __shfl_xor_sync(0xffffffffu, q, o); }
    if (lane == 0){ wsum[w] = s; wsq[w] = q; }
    __syncthreads();
    if (tid == 0){
        float S = 0.f, Q = 0.f;
        #pragma unroll
        for (int i = 0; i < 8; i++){ S += wsum[i]; Q += wsq[i]; }
        float m = S * (1.f/768.f); float var = Q * (1.f/768.f) - m*m;
        wsum[0] = m; wsq[0] = rsqrtf(var + EPSV);
    }
    __syncthreads();
    float m = wsum[0], r = wsq[0];
    for (int i = tid; i < 768; i += 256)
        g_cn[((size_t)b*768 + i)*77 + n] = (row[i] - m) * r * gg[i] + gb[i];
}

// ---------------- q softmax over head-dim (64 rows) at fixed (b,t) ----------
__global__ void k_qsm(float* __restrict__ q){
    __shared__ float tile[64][32];
    __shared__ float red[8][32];
    __shared__ float colm[32], cols[32];
    int t0 = blockIdx.x*32, h = blockIdx.y, b = blockIdx.z;
    int tid = threadIdx.x, col = tid & 31, seg = tid >> 5;
    size_t base = ((size_t)(b*512 + h*64))*512 + t0;
    #pragma unroll
    for (int k = 0; k < 8; k++){
        int idx = k*256 + tid; int r = idx >> 5, c = idx & 31;
        tile[r][c] = q[base + (size_t)r*512 + c];
    }
    __syncthreads();
    float m = -1e30f;
    #pragma unroll
    for (int r = 0; r < 8; r++) m = fmaxf(m, tile[seg*8 + r][col]);
    red[seg][col] = m;
    __syncthreads();
    if (tid < 32){
        float mm = red[0][tid];
        #pragma unroll
        for (int w = 1; w < 8; w++) mm = fmaxf(mm, red[w][tid]);
        colm[tid] = mm;
    }
    __syncthreads();
    float s = 0.f;
    #pragma unroll
    for (int r = 0; r < 8; r++) s += expf(tile[seg*8 + r][col] - colm[col]);
    red[seg][col] = s;
    __syncthreads();
    if (tid < 32){
        float ss2 = 0.f;
        #pragma unroll
        for (int w = 0; w < 8; w++) ss2 += red[w][tid];
        cols[tid] = 1.f / ss2;
    }
    __syncthreads();
    #pragma unroll
    for (int k = 0; k < 8; k++){
        int idx = k*256 + tid; int r = idx >> 5, c = idx & 31;
        q[base + (size_t)r*512 + c] = expf(tile[r][c] - colm[c]) * cols[c];
    }
}

// ---------------- k softmax over n (77) at fixed (b,d) ----------------------
__global__ void k_ksm(float* __restrict__ kbuf){
    int b = blockIdx.x;
    int d = blockIdx.y*8 + (threadIdx.x >> 5);
    int lane = threadIdx.x & 31;
    float* row = kbuf + ((size_t)b*512 + d)*77;
    float v0 = row[lane];
    float v1 = row[lane + 32];
    bool has2 = (lane + 64) < 77;
    float v2 = has2 ? row[lane + 64] : -1e30f;
    float m = fmaxf(fmaxf(v0, v1), v2);
    #pragma unroll
    for (int o = 16; o; o >>= 1) m = fmaxf(m, __shfl_xor_sync(0xffffffffu, m, o));
    float e0 = expf(v0 - m), e1 = expf(v1 - m), e2 = has2 ? expf(v2 - m) : 0.f;
    float s = e0 + e1 + e2;
    #pragma unroll
    for (int o = 16; o; o >>= 1) s += __shfl_xor_sync(0xffffffffu, s, o);
    float inv = 1.f / s;
    row[lane] = e0 * inv;
    row[lane + 32] = e1 * inv;
    if (has2) row[lane + 64] = e2 * inv;
}

// ---------------- attn[b,h,d,l] = sum_n k[b,hd+d,n] * v[b,hd+l,n] ------------
__global__ void k_attn(const float* __restrict__ kbuf, const float* __restrict__ vbuf){
    __shared__ float ks[64][80], vs[64][80];
    int h = blockIdx.x, b = blockIdx.y;
    int tid = threadIdx.x, tx = tid & 15, ty = tid >> 4;
    const float* kp = kbuf + ((size_t)(b*512 + h*64))*77;
    const float* vp = vbuf + ((size_t)(b*512 + h*64))*77;
    for (int idx = tid; idx < 64*80; idx += 256){
        int r = idx / 80, c = idx - r*80;
        float kv = (c < 77) ? kp[(size_t)r*77 + c] : 0.f;
        float vv = (c < 77) ? vp[(size_t)r*77 + c] : 0.f;
        ks[r][c] = kv; vs[r][c] = vv;
    }
    __syncthreads();
    float acc[4][4];
    #pragma unroll
    for (int i = 0; i < 4; i++)
        #pragma unroll
        for (int j = 0; j < 4; j++) acc[i][j] = 0.f;
    for (int n = 0; n < 77; n++){
        float a[4], c4[4];
        #pragma unroll
        for (int i = 0; i < 4; i++) a[i] = ks[ty*4 + i][n];
        #pragma unroll
        for (int j = 0; j < 4; j++) c4[j] = vs[tx*4 + j][n];
        #pragma unroll
        for (int i = 0; i < 4; i++)
            #pragma unroll
            for (int j = 0; j < 4; j++) acc[i][j] = fmaf(a[i], c4[j], acc[i][j]);
    }
    #pragma unroll
    for (int i = 0; i < 4; i++)
        #pragma unroll
        for (int j = 0; j < 4; j++)
            g_attn[(((size_t)(b*8 + h))*64 + ty*4 + i)*64 + tx*4 + j] = acc[i][j];
}

// ---------------- y = q @ attn, scatter-add into d_out ----------------------
// grid (4 ttiles, 8 h, 64 b); y[t,l] = sum_d q[b,hd+d,t]*attn[b,h,d,l]
__global__ void k_y(const float* __restrict__ q, float* __restrict__ out,
                    const int* __restrict__ cidx){
    __shared__ __align__(16) float qs[64][128];
    __shared__ float as[64][64];
    int t0 = blockIdx.x*128, h = blockIdx.y, b = blockIdx.z;
    int bi = cidx[b];
    int tid = threadIdx.x, tx = tid & 15, ty = tid >> 4;
    for (int idx = tid; idx < 64*128; idx += 256){
        int r = idx >> 7, c = idx & 127;
        qs[r][c] = q[((size_t)(b*512 + h*64 + r))*512 + t0 + c];
    }
    for (int idx = tid; idx < 64*64; idx += 256){
        int r = idx >> 6, c = idx & 63;
        as[r][c] = g_attn[(((size_t)(b*8 + h))*64 + r)*64 + c];
    }
    __syncthreads();
    float acc[4][8];
    #pragma unroll
    for (int i = 0; i < 4; i++)
        #pragma unroll
        for (int j = 0; j < 8; j++) acc[i][j] = 0.f;
    for (int d = 0; d < 64; d++){
        float4 q0 = *reinterpret_cast<const float4*>(&qs[d][tx*8]);
        float4 q1 = *reinterpret_cast<const float4*>(&qs[d][tx*8 + 4]);
        float qr[8] = {q0.x,q0.y,q0.z,q0.w,q1.x,q1.y,q1.z,q1.w};
        float ar[4];
        #pragma unroll
        for (int i = 0; i < 4; i++) ar[i] = as[d][ty*4 + i];
        #pragma unroll
        for (int i = 0; i < 4; i++)
            #pragma unroll
            for (int j = 0; j < 8; j++) acc[i][j] = fmaf(ar[i], qr[j], acc[i][j]);
    }
    #pragma unroll
    for (int i = 0; i < 4; i++){
        int ch = h*64 + ty*4 + i;
        #pragma unroll
        for (int j = 0; j < 8; j++){
            atomicAdd(&out[((size_t)bi*512 + ch)*512 + t0 + tx*8 + j], acc[i][j]);
        }
    }
}

// ---------------- launch ----------------------------------------------------
extern "C" void kernel_launch(void* const* d_in, const int* in_sizes, int n_in,
                              void* d_out, int out_size){
    const float* x       = (const float*)d_in[0];
    const float* t       = (const float*)d_in[1];
    const float* cond    = (const float*)d_in[2];
    const float* conv0_w = (const float*)d_in[3];
    const float* conv0_b = (const float*)d_in[4];
    const float* gn0_g   = (const float*)d_in[5];
    const float* gn0_b   = (const float*)d_in[6];
    const float* tm_w    = (const float*)d_in[7];
    const float* tm_b    = (const float*)d_in[8];
    const float* conv1_w = (const float*)d_in[9];
    const float* conv1_b = (const float*)d_in[10];
    const float* gn1_g   = (const float*)d_in[11];
    const float* gn1_b   = (const float*)d_in[12];
    const float* res_w   = (const float*)d_in[13];
    const float* res_b   = (const float*)d_in[14];
    const float* ln_x_g  = (const float*)d_in[15];
    const float* ln_x_b  = (const float*)d_in[16];
    const float* ln_c_g  = (const float*)d_in[17];
    const float* ln_c_b  = (const float*)d_in[18];
    const float* q_w     = (const float*)d_in[19];
    const float* q_b     = (const float*)d_in[20];
    const float* k_w     = (const float*)d_in[21];
    const float* k_b     = (const float*)d_in[22];
    const float* v_w     = (const float*)d_in[23];
    const float* v_b     = (const float*)d_in[24];
    const int*   cidx    = (const int*)d_in[25];
    float* out = (float*)d_out;

    float *p_h, *p_h2, *p_xln, *p_q, *p_cn, *p_k, *p_v;
    cudaGetSymbolAddress((void**)&p_h,   g_h);
    cudaGetSymbolAddress((void**)&p_h2,  g_h2);
    cudaGetSymbolAddress((void**)&p_xln, g_xln);
    cudaGetSymbolAddress((void**)&p_q,   g_q);
    cudaGetSymbolAddress((void**)&p_cn,  g_cn);
    cudaGetSymbolAddress((void**)&p_k,   g_k);
    cudaGetSymbolAddress((void**)&p_v,   g_v);

    // FiLM scale/shift
    k_ss<<<64, 256>>>(t, tm_w, tm_b);
    // conv0 -> g_h
    k_conv<256,5,2><<<dim3(4,8,64), 256>>>(x, conv0_w, conv0_b, p_h, 512);
    // gn0 + FiLM + mish -> g_h2
    k_gn0<<<dim3(16,8,64), 256>>>(p_h, gn0_g, gn0_b, p_h2);
    // conv1 -> g_h
    k_conv<512,5,2><<<dim3(4,8,64), 256>>>(p_h2, conv1_w, conv1_b, p_h, 512);
    // residual 1x1 conv -> d_out
    k_conv<256,1,0><<<dim3(4,8,64), 256>>>(x, res_w, res_b, out, 512);
    // out = mish(gn1(conv1)) + res  (in-place on d_out)
    k_gn1<<<dim3(16,8,64), 256>>>(p_h, gn1_g, gn1_b, out);
    // LN over channels of out[cidx] -> g_xln (b,c,t)
    k_xln<<<dim3(4,64), 128>>>(out, ln_x_g, ln_x_b, cidx);
    // q projection (1x1 conv) -> g_q (b,d,t)
    k_conv<512,1,0><<<dim3(4,8,64), 256>>>(p_xln, q_w, q_b, p_q, 512);
    // q softmax over head-dim
    k_qsm<<<dim3(16,8,64), 256>>>(p_q);
    // LN(cond[cidx]) -> g_cn (b, 768, 77)
    k_cn<<<dim3(77,64), 256>>>(cond, ln_c_g, ln_c_b, cidx);
    // k,v projections (1x1 conv over 768 ch, L=77)
    k_conv<768,1,0><<<dim3(1,8,64), 256>>>(p_cn, k_w, k_b, p_k, 77);
    k_conv<768,1,0><<<dim3(1,8,64), 256>>>(p_cn, v_w, v_b, p_v, 77);
    // k softmax over n
    k_ksm<<<dim3(64,64), 256>>>(p_k);
    // attn = k^T v per (b,h)
    k_attn<<<dim3(8,64), 256>>>(p_k, p_v);
    // y = q @ attn, scatter-add into d_out
    k_y<<<dim3(4,8,64), 256>>>(p_q, out, cidx);
}

// round 2
// speedup vs baseline: 1.0447x; 1.0447x over previous
#include <cuda_runtime.h>
#include <math.h>

#define EPSV 1e-5f

// ---------------- scratch (allocation-free: device globals) ----------------
__device__ float g_ss  [64*1024];
__device__ float g_h   [64*512*512];
__device__ float g_h2  [64*512*512];
__device__ float g_xln [64*512*512];
__device__ float g_q   [64*512*512];
__device__ float g_cn  [64*768*77];
__device__ float g_k   [64*512*77];
__device__ float g_v   [64*512*77];
__device__ float g_attn[64*8*64*64];

__device__ __forceinline__ float mishf(float x){
    float sp = fmaxf(x, 0.f) + log1pf(expf(-fabsf(x)));
    return x * tanhf(sp);
}

// ---------------- packed f32x2 helpers (Blackwell FFMA2 path) ---------------
__device__ __forceinline__ unsigned long long pack2(float lo, float hi){
    unsigned long long r;
    asm("mov.b64 %0, {%1,%2};" : "=l"(r) : "f"(lo), "f"(hi));
    return r;
}
__device__ __forceinline__ void fma2(unsigned long long &acc,
                                     unsigned long long a, unsigned long long b){
    asm("fma.rn.f32x2 %0, %1, %2, %0;" : "+l"(acc) : "l"(a), "l"(b));
}
__device__ __forceinline__ void unpack2(unsigned long long v, float &lo, float &hi){
    asm("mov.b64 {%0,%1}, %2;" : "=f"(lo), "=f"(hi) : "l"(v));
}

// ---------------- ss = mish(t) @ tm_w^T + tm_b -----------------------------
__global__ void k_ss(const float* __restrict__ t, const float* __restrict__ w,
                     const float* __restrict__ bias){
    __shared__ float tm[512];
    int b = blockIdx.x, tid = threadIdx.x;
    for (int i = tid; i < 512; i += 256) tm[i] = mishf(t[b*512 + i]);
    __syncthreads();
    for (int o = tid; o < 1024; o += 256){
        const float* wr = w + (size_t)o * 512;
        float acc = bias[o];
        #pragma unroll 8
        for (int i = 0; i < 512; i++) acc = fmaf(tm[i], wr[i], acc);
        g_ss[b*1024 + o] = acc;
    }
}

// ---------------- generic conv1d (GEMM-style, FFMA2 inner loop) -------------
// out[b,co,l] = bias[co] + sum_{ci,k} w[co,ci,k] * in[b,ci,l+k-PAD]
// grid: (ceil(L/128), Cout/64, B), block 256. 4 co x 8 l per thread.
// Accumulators packed over adjacent co pairs -> fma.rn.f32x2.
template<int CIN, int TAPS, int PAD>
__global__ void k_conv(const float* __restrict__ in, const float* __restrict__ w,
                       const float* __restrict__ bias, float* __restrict__ out, int L){
    constexpr int LW  = 128 + TAPS - 1;
    constexpr int NXR = 8 + TAPS - 1;
    constexpr int CPAD = 66;                 // 64 channels + pad (keeps 8B align, kills conflicts)
    __shared__ __align__(16) float xs[16][LW];
    __shared__ __align__(8)  float ws[16][TAPS][CPAD];
    const int l0  = blockIdx.x * 128;
    const int co0 = blockIdx.y * 64;
    const int b   = blockIdx.z;
    const int COUT = gridDim.y * 64;
    const int tid = threadIdx.x, tx = tid & 15, ty = tid >> 4;

    unsigned long long acc2[2][8];
    #pragma unroll
    for (int p = 0; p < 2; p++)
        #pragma unroll
        for (int j = 0; j < 8; j++) acc2[p][j] = 0ull;

    const float* inb = in + (size_t)b * CIN * L;

    for (int ci0 = 0; ci0 < CIN; ci0 += 16){
        for (int idx = tid; idx < 16*LW; idx += 256){
            int r = idx / LW, cc = idx - r*LW;
            int l = l0 + cc - PAD;
            xs[r][cc] = (l >= 0 && l < L) ? inb[(size_t)(ci0 + r)*L + l] : 0.f;
        }
        // weights: global read contiguous per-channel (80/16 elems), write transposed [i][k][c]
        for (int idx = tid; idx < 64*16*TAPS; idx += 256){
            int c = idx / (16*TAPS); int rem = idx - c*16*TAPS;
            int i = rem / TAPS;      int k = rem - i*TAPS;
            ws[i][k][c] = w[((size_t)(co0 + c)*CIN + ci0 + i)*TAPS + k];
        }
        __syncthreads();
        #pragma unroll
        for (int i = 0; i < 16; i++){
            float xr[NXR];
            #pragma unroll
            for (int v = 0; v < NXR/4; v++){
                float4 t4 = *reinterpret_cast<const float4*>(&xs[i][tx*8 + v*4]);
                xr[v*4+0] = t4.x; xr[v*4+1] = t4.y; xr[v*4+2] = t4.z; xr[v*4+3] = t4.w;
            }
            unsigned long long xb[NXR];
            #pragma unroll
            for (int s = 0; s < NXR; s++) xb[s] = pack2(xr[s], xr[s]);
            #pragma unroll
            for (int k = 0; k < TAPS; k++){
                unsigned long long w0 =
                    *reinterpret_cast<const unsigned long long*>(&ws[i][k][ty*4]);
                unsigned long long w1 =
                    *reinterpret_cast<const unsigned long long*>(&ws[i][k][ty*4 + 2]);
                #pragma unroll
                for (int j = 0; j < 8; j++){
                    fma2(acc2[0][j], w0, xb[j + k]);
                    fma2(acc2[1][j], w1, xb[j + k]);
                }
            }
        }
        __syncthreads();
    }
    #pragma unroll
    for (int p = 0; p < 2; p++){
        int c0 = co0 + ty*4 + p*2;
        float b0 = bias[c0], b1 = bias[c0 + 1];
        #pragma unroll
        for (int j = 0; j < 8; j++){
            float vlo, vhi;
            unpack2(acc2[p][j], vlo, vhi);
            int l = l0 + tx*8 + j;
            if (l < L){
                out[((size_t)b*COUT + c0    )*L + l] = vlo + b0;
                out[((size_t)b*COUT + c0 + 1)*L + l] = vhi + b1;
            }
        }
    }
}

// ---------------- GN0 + FiLM + mish -----------------------------------------
__global__ void k_gn0(const float* __restrict__ in, const float* __restrict__ gg,
                      const float* __restrict__ gb, float* __restrict__ out){
    __shared__ float tile[64][32];
    __shared__ float rs[8][32], rq[8][32];
    __shared__ float cm[32], cr[32];
    int l0 = blockIdx.x*32, g = blockIdx.y, b = blockIdx.z;
    int tid = threadIdx.x, col = tid & 31, seg = tid >> 5;
    size_t base = ((size_t)(b*512 + g*64))*512 + l0;
    #pragma unroll
    for (int k = 0; k < 8; k++){
        int idx = k*256 + tid; int r = idx >> 5, c = idx & 31;
        tile[r][c] = in[base + (size_t)r*512 + c];
    }
    __syncthreads();
    float s = 0.f, q = 0.f;
    #pragma unroll
    for (int r = 0; r < 8; r++){ float v = tile[seg*8 + r][col]; s += v; q += v*v; }
    rs[seg][col] = s; rq[seg][col] = q;
    __syncthreads();
    if (tid < 32){
        float S = 0.f, Q = 0.f;
        #pragma unroll
        for (int w = 0; w < 8; w++){ S += rs[w][tid]; Q += rq[w][tid]; }
        float m = S * (1.f/64.f); float var = Q * (1.f/64.f) - m*m;
        cm[tid] = m; cr[tid] = rsqrtf(var + EPSV);
    }
    __syncthreads();
    #pragma unroll
    for (int k = 0; k < 8; k++){
        int idx = k*256 + tid; int r = idx >> 5, c = idx & 31;
        int ch = g*64 + r;
        float v = (tile[r][c] - cm[c]) * cr[c] * gg[ch] + gb[ch];
        float sc = g_ss[b*1024 + ch], sh = g_ss[b*1024 + 512 + ch];
        v = v * (1.f + sc) + sh;
        out[base + (size_t)r*512 + c] = mishf(v);
    }
}

// ---------------- GN1 + mish + residual add (in-place on d_out) -------------
__global__ void k_gn1(const float* __restrict__ in, const float* __restrict__ gg,
                      const float* __restrict__ gb, float* __restrict__ dout){
    __shared__ float tile[64][32];
    __shared__ float rs[8][32], rq[8][32];
    __shared__ float cm[32], cr[32];
    int l0 = blockIdx.x*32, g = blockIdx.y, b = blockIdx.z;
    int tid = threadIdx.x, col = tid & 31, seg = tid >> 5;
    size_t base = ((size_t)(b*512 + g*64))*512 + l0;
    #pragma unroll
    for (int k = 0; k < 8; k++){
        int idx = k*256 + tid; int r = idx >> 5, c = idx & 31;
        tile[r][c] = in[base + (size_t)r*512 + c];
    }
    __syncthreads();
    float s = 0.f, q = 0.f;
    #pragma unroll
    for (int r = 0; r < 8; r++){ float v = tile[seg*8 + r][col]; s += v; q += v*v; }
    rs[seg][col] = s; rq[seg][col] = q;
    __syncthreads();
    if (tid < 32){
        float S = 0.f, Q = 0.f;
        #pragma unroll
        for (int w = 0; w < 8; w++){ S += rs[w][tid]; Q += rq[w][tid]; }
        float m = S * (1.f/64.f); float var = Q * (1.f/64.f) - m*m;
        cm[tid] = m; cr[tid] = rsqrtf(var + EPSV);
    }
    __syncthreads();
    #pragma unroll
    for (int k = 0; k < 8; k++){
        int idx = k*256 + tid; int r = idx >> 5, c = idx & 31;
        int ch = g*64 + r;
        float v = (tile[r][c] - cm[c]) * cr[c] * gg[ch] + gb[ch];
        size_t o = base + (size_t)r*512 + c;
        dout[o] = mishf(v) + dout[o];
    }
}

// ---------------- LN over channels of out[cidx[b]] -> g_xln (b,c,t) ---------
__global__ void k_xln(const float* __restrict__ out, const float* __restrict__ gg,
                      const float* __restrict__ gb, const int* __restrict__ cidx){
    int b = blockIdx.y;
    int t = blockIdx.x*128 + threadIdx.x;
    int bi = cidx[b];
    const float* src = out + (size_t)bi*512*512 + t;
    float s = 0.f, q = 0.f;
    for (int c = 0; c < 512; c++){ float v = src[(size_t)c*512]; s += v; q += v*v; }
    float m = s * (1.f/512.f);
    float r = rsqrtf(q * (1.f/512.f) - m*m + EPSV);
    float* dst = g_xln + (size_t)b*512*512 + t;
    for (int c = 0; c < 512; c++){
        float v = src[(size_t)c*512];
        dst[(size_t)c*512] = (v - m) * r * gg[c] + gb[c];
    }
}

// ---------------- LN(cond[cidx[b]]) -> g_cn (b, 768, 77) transposed ---------
__global__ void k_cn(const float* __restrict__ cond, const float* __restrict__ gg,
                     const float* __restrict__ gb, const int* __restrict__ cidx){
    __shared__ float row[768];
    __shared__ float wsum[8], wsq[8];
    int n = blockIdx.x, b = blockIdx.y;
    int bi = cidx[b];
    int tid = threadIdx.x, lane = tid & 31, w = tid >> 5;
    const float* src = cond + ((size_t)bi*77 + n)*768;
    float s = 0.f, q = 0.f;
    for (int i = tid; i < 768; i += 256){ float v = src[i]; row[i] = v; s += v; q += v*v; }
    #pragma unroll
    for (int o = 16; o; o >>= 1){ s += __shfl_xor_sync(0xffffffffu, s, o); q += __shfl_xor_sync(0xffffffffu, q, o); }
    if (lane == 0){ wsum[w] = s; wsq[w] = q; }
    __syncthreads();
    if (tid == 0){
        float S = 0.f, Q = 0.f;
        #pragma unroll
        for (int i = 0; i < 8; i++){ S += wsum[i]; Q += wsq[i]; }
        float m = S * (1.f/768.f); float var = Q * (1.f/768.f) - m*m;
        wsum[0] = m; wsq[0] = rsqrtf(var + EPSV);
    }
    __syncthreads();
    float m = wsum[0], r = wsq[0];
    for (int i = tid; i < 768; i += 256)
        g_cn[((size_t)b*768 + i)*77 + n] = (row[i] - m) * r * gg[i] + gb[i];
}

// ---------------- q softmax over head-dim (64 rows) at fixed (b,t) ----------
__global__ void k_qsm(float* __restrict__ q){
    __shared__ float tile[64][32];
    __shared__ float red[8][32];
    __shared__ float colm[32], cols[32];
    int t0 = blockIdx.x*32, h = blockIdx.y, b = blockIdx.z;
    int tid = threadIdx.x, col = tid & 31, seg = tid >> 5;
    size_t base = ((size_t)(b*512 + h*64))*512 + t0;
    #pragma unroll
    for (int k = 0; k < 8; k++){
        int idx = k*256 + tid; int r = idx >> 5, c = idx & 31;
        tile[r][c] = q[base + (size_t)r*512 + c];
    }
    __syncthreads();
    float m = -1e30f;
    #pragma unroll
    for (int r = 0; r < 8; r++) m = fmaxf(m, tile[seg*8 + r][col]);
    red[seg][col] = m;
    __syncthreads();
    if (tid < 32){
        float mm = red[0][tid];
        #pragma unroll
        for (int w = 1; w < 8; w++) mm = fmaxf(mm, red[w][tid]);
        colm[tid] = mm;
    }
    __syncthreads();
    float s = 0.f;
    #pragma unroll
    for (int r = 0; r < 8; r++) s += expf(tile[seg*8 + r][col] - colm[col]);
    red[seg][col] = s;
    __syncthreads();
    if (tid < 32){
        float ss2 = 0.f;
        #pragma unroll
        for (int w = 0; w < 8; w++) ss2 += red[w][tid];
        cols[tid] = 1.f / ss2;
    }
    __syncthreads();
    #pragma unroll
    for (int k = 0; k < 8; k++){
        int idx = k*256 + tid; int r = idx >> 5, c = idx & 31;
        q[base + (size_t)r*512 + c] = expf(tile[r][c] - colm[c]) * cols[c];
    }
}

// ---------------- k softmax over n (77) at fixed (b,d) ----------------------
__global__ void k_ksm(float* __restrict__ kbuf){
    int b = blockIdx.x;
    int d = blockIdx.y*8 + (threadIdx.x >> 5);
    int lane = threadIdx.x & 31;
    float* row = kbuf + ((size_t)b*512 + d)*77;
    float v0 = row[lane];
    float v1 = row[lane + 32];
    bool has2 = (lane + 64) < 77;
    float v2 = has2 ? row[lane + 64] : -1e30f;
    float m = fmaxf(fmaxf(v0, v1), v2);
    #pragma unroll
    for (int o = 16; o; o >>= 1) m = fmaxf(m, __shfl_xor_sync(0xffffffffu, m, o));
    float e0 = expf(v0 - m), e1 = expf(v1 - m), e2 = has2 ? expf(v2 - m) : 0.f;
    float s = e0 + e1 + e2;
    #pragma unroll
    for (int o = 16; o; o >>= 1) s += __shfl_xor_sync(0xffffffffu, s, o);
    float inv = 1.f / s;
    row[lane] = e0 * inv;
    row[lane + 32] = e1 * inv;
    if (has2) row[lane + 64] = e2 * inv;
}

// ---------------- attn[b,h,d,l] = sum_n k[b,hd+d,n] * v[b,hd+l,n] ------------
__global__ void k_attn(const float* __restrict__ kbuf, const float* __restrict__ vbuf){
    __shared__ float ks[64][80], vs[64][80];
    int h = blockIdx.x, b = blockIdx.y;
    int tid = threadIdx.x, tx = tid & 15, ty = tid >> 4;
    const float* kp = kbuf + ((size_t)(b*512 + h*64))*77;
    const float* vp = vbuf + ((size_t)(b*512 + h*64))*77;
    for (int idx = tid; idx < 64*80; idx += 256){
        int r = idx / 80, c = idx - r*80;
        float kv = (c < 77) ? kp[(size_t)r*77 + c] : 0.f;
        float vv = (c < 77) ? vp[(size_t)r*77 + c] : 0.f;
        ks[r][c] = kv; vs[r][c] = vv;
    }
    __syncthreads();
    float acc[4][4];
    #pragma unroll
    for (int i = 0; i < 4; i++)
        #pragma unroll
        for (int j = 0; j < 4; j++) acc[i][j] = 0.f;
    for (int n = 0; n < 77; n++){
        float a[4], c4[4];
        #pragma unroll
        for (int i = 0; i < 4; i++) a[i] = ks[ty*4 + i][n];
        #pragma unroll
        for (int j = 0; j < 4; j++) c4[j] = vs[tx*4 + j][n];
        #pragma unroll
        for (int i = 0; i < 4; i++)
            #pragma unroll
            for (int j = 0; j < 4; j++) acc[i][j] = fmaf(a[i], c4[j], acc[i][j]);
    }
    #pragma unroll
    for (int i = 0; i < 4; i++)
        #pragma unroll
        for (int j = 0; j < 4; j++)
            g_attn[(((size_t)(b*8 + h))*64 + ty*4 + i)*64 + tx*4 + j] = acc[i][j];
}

// ---------------- y = q @ attn, scatter-add into d_out ----------------------
__global__ void k_y(const float* __restrict__ q, float* __restrict__ out,
                    const int* __restrict__ cidx){
    __shared__ __align__(16) float qs[64][128];
    __shared__ float as[64][64];
    int t0 = blockIdx.x*128, h = blockIdx.y, b = blockIdx.z;
    int bi = cidx[b];
    int tid = threadIdx.x, tx = tid & 15, ty = tid >> 4;
    for (int idx = tid; idx < 64*128; idx += 256){
        int r = idx >> 7, c = idx & 127;
        qs[r][c] = q[((size_t)(b*512 + h*64 + r))*512 + t0 + c];
    }
    for (int idx = tid; idx < 64*64; idx += 256){
        int r = idx >> 6, c = idx & 63;
        as[r][c] = g_attn[(((size_t)(b*8 + h))*64 + r)*64 + c];
    }
    __syncthreads();
    float acc[4][8];
    #pragma unroll
    for (int i = 0; i < 4; i++)
        #pragma unroll
        for (int j = 0; j < 8; j++) acc[i][j] = 0.f;
    for (int d = 0; d < 64; d++){
        float4 q0 = *reinterpret_cast<const float4*>(&qs[d][tx*8]);
        float4 q1 = *reinterpret_cast<const float4*>(&qs[d][tx*8 + 4]);
        float qr[8] = {q0.x,q0.y,q0.z,q0.w,q1.x,q1.y,q1.z,q1.w};
        float ar[4];
        #pragma unroll
        for (int i = 0; i < 4; i++) ar[i] = as[d][ty*4 + i];
        #pragma unroll
        for (int i = 0; i < 4; i++)
            #pragma unroll
            for (int j = 0; j < 8; j++) acc[i][j] = fmaf(ar[i], qr[j], acc[i][j]);
    }
    #pragma unroll
    for (int i = 0; i < 4; i++){
        int ch = h*64 + ty*4 + i;
        #pragma unroll
        for (int j = 0; j < 8; j++){
            atomicAdd(&out[((size_t)bi*512 + ch)*512 + t0 + tx*8 + j], acc[i][j]);
        }
    }
}

// ---------------- launch ----------------------------------------------------
extern "C" void kernel_launch(void* const* d_in, const int* in_sizes, int n_in,
                              void* d_out, int out_size){
    const float* x       = (const float*)d_in[0];
    const float* t       = (const float*)d_in[1];
    const float* cond    = (const float*)d_in[2];
    const float* conv0_w = (const float*)d_in[3];
    const float* conv0_b = (const float*)d_in[4];
    const float* gn0_g   = (const float*)d_in[5];
    const float* gn0_b   = (const float*)d_in[6];
    const float* tm_w    = (const float*)d_in[7];
    const float* tm_b    = (const float*)d_in[8];
    const float* conv1_w = (const float*)d_in[9];
    const float* conv1_b = (const float*)d_in[10];
    const float* gn1_g   = (const float*)d_in[11];
    const float* gn1_b   = (const float*)d_in[12];
    const float* res_w   = (const float*)d_in[13];
    const float* res_b   = (const float*)d_in[14];
    const float* ln_x_g  = (const float*)d_in[15];
    const float* ln_x_b  = (const float*)d_in[16];
    const float* ln_c_g  = (const float*)d_in[17];
    const float* ln_c_b  = (const float*)d_in[18];
    const float* q_w     = (const float*)d_in[19];
    const float* q_b     = (const float*)d_in[20];
    const float* k_w     = (const float*)d_in[21];
    const float* k_b     = (const float*)d_in[22];
    const float* v_w     = (const float*)d_in[23];
    const float* v_b     = (const float*)d_in[24];
    const int*   cidx    = (const int*)d_in[25];
    float* out = (float*)d_out;

    float *p_h, *p_h2, *p_xln, *p_q, *p_cn, *p_k, *p_v;
    cudaGetSymbolAddress((void**)&p_h,   g_h);
    cudaGetSymbolAddress((void**)&p_h2,  g_h2);
    cudaGetSymbolAddress((void**)&p_xln, g_xln);
    cudaGetSymbolAddress((void**)&p_q,   g_q);
    cudaGetSymbolAddress((void**)&p_cn,  g_cn);
    cudaGetSymbolAddress((void**)&p_k,   g_k);
    cudaGetSymbolAddress((void**)&p_v,   g_v);

    // FiLM scale/shift
    k_ss<<<64, 256>>>(t, tm_w, tm_b);
    // conv0 -> g_h
    k_conv<256,5,2><<<dim3(4,8,64), 256>>>(x, conv0_w, conv0_b, p_h, 512);
    // gn0 + FiLM + mish -> g_h2
    k_gn0<<<dim3(16,8,64), 256>>>(p_h, gn0_g, gn0_b, p_h2);
    // conv1 -> g_h
    k_conv<512,5,2><<<dim3(4,8,64), 256>>>(p_h2, conv1_w, conv1_b, p_h, 512);
    // residual 1x1 conv -> d_out
    k_conv<256,1,0><<<dim3(4,8,64), 256>>>(x, res_w, res_b, out, 512);
    // out = mish(gn1(conv1)) + res  (in-place on d_out)
    k_gn1<<<dim3(16,8,64), 256>>>(p_h, gn1_g, gn1_b, out);
    // LN over channels of out[cidx] -> g_xln (b,c,t)
    k_xln<<<dim3(4,64), 128>>>(out, ln_x_g, ln_x_b, cidx);
    // q projection (1x1 conv) -> g_q (b,d,t)
    k_conv<512,1,0><<<dim3(4,8,64), 256>>>(p_xln, q_w, q_b, p_q, 512);
    // q softmax over head-dim
    k_qsm<<<dim3(16,8,64), 256>>>(p_q);
    // LN(cond[cidx]) -> g_cn (b, 768, 77)
    k_cn<<<dim3(77,64), 256>>>(cond, ln_c_g, ln_c_b, cidx);
    // k,v projections (1x1 conv over 768 ch, L=77)
    k_conv<768,1,0><<<dim3(1,8,64), 256>>>(p_cn, k_w, k_b, p_k, 77);
    k_conv<768,1,0><<<dim3(1,8,64), 256>>>(p_cn, v_w, v_b, p_v, 77);
    // k softmax over n
    k_ksm<<<dim3(64,64), 256>>>(p_k);
    // attn = k^T v per (b,h)
    k_attn<<<dim3(8,64), 256>>>(p_k, p_v);
    // y = q @ attn, scatter-add into d_out
    k_y<<<dim3(4,8,64), 256>>>(p_q, out, cidx);
}

// round 3
// speedup vs baseline: 1.8968x; 1.8157x over previous
#include <cuda_runtime.h>
#include <math.h>
#include <stdint.h>

#define EPSV 1e-5f

// ---------------- scratch (allocation-free: device globals) ----------------
__device__ float g_ss  [64*1024];
__device__ float g_h   [64*512*512];
__device__ float g_h2  [64*512*512];
__device__ float g_xln [64*512*512];
__device__ float g_q   [64*512*512];
__device__ float g_cn  [64*768*77];
__device__ float g_k   [64*512*77];
__device__ float g_v   [64*512*77];
__device__ float g_attn[64*8*64*64];

__device__ __forceinline__ float mishf(float x){
    float sp = fmaxf(x, 0.f) + log1pf(expf(-fabsf(x)));
    return x * tanhf(sp);
}

// ---------------- tf32 mma helpers ------------------------------------------
__device__ __forceinline__ uint32_t f2tf32(float f){
    uint32_t r; asm("cvt.rna.tf32.f32 %0, %1;" : "=r"(r) : "f"(f)); return r;
}
__device__ __forceinline__ void mma_tf32(float* c, const uint32_t* a, const uint32_t* b){
    asm("mma.sync.aligned.m16n8k8.row.col.f32.tf32.tf32.f32 "
        "{%0,%1,%2,%3}, {%4,%5,%6,%7}, {%8,%9}, {%0,%1,%2,%3};"
        : "+f"(c[0]), "+f"(c[1]), "+f"(c[2]), "+f"(c[3])
        : "r"(a[0]), "r"(a[1]), "r"(a[2]), "r"(a[3]), "r"(b[0]), "r"(b[1]));
}

// ---------------- ss = mish(t) @ tm_w^T + tm_b -----------------------------
__global__ void k_ss(const float* __restrict__ t, const float* __restrict__ w,
                     const float* __restrict__ bias){
    __shared__ float tm[512];
    int b = blockIdx.x, tid = threadIdx.x;
    for (int i = tid; i < 512; i += 256) tm[i] = mishf(t[b*512 + i]);
    __syncthreads();
    for (int o = tid; o < 1024; o += 256){
        const float* wr = w + (size_t)o * 512;
        float acc = bias[o];
        #pragma unroll 8
        for (int i = 0; i < 512; i++) acc = fmaf(tm[i], wr[i], acc);
        g_ss[b*1024 + o] = acc;
    }
}

// ---------------- conv1d as implicit GEMM on tf32 tensor cores --------------
// out[b,co,l] = bias[co] + sum_{ci,k} w[co,ci,k] * in[b,ci,l+k-PAD]
// Block: 256 thr = 8 warps (2m x 4n). Block tile M=64(co) x N=128(l).
// K loop: 16 input channels per chunk, taps as micro-loop (shifted xs reads).
template<int CIN, int TAPS, int PAD>
__global__ void k_conv(const float* __restrict__ in, const float* __restrict__ w,
                       const float* __restrict__ bias, float* __restrict__ out, int L){
    constexpr int LWD = 128 + TAPS - 1;   // valid data columns in xs
    constexpr int LWS = 136;              // padded row stride (8 mod 32 banks)
    constexpr int KCH = 16*TAPS;          // weights per co per chunk
    constexpr int WST = KCH + 4;          // ws row stride (conflict-free)
    __shared__ float xs[16][LWS];
    __shared__ float ws[64][WST];
    const int l0 = blockIdx.x*128, co0 = blockIdx.y*64, b = blockIdx.z;
    const int COUT = gridDim.y*64;
    const int tid = threadIdx.x, lane = tid & 31, wid = tid >> 5;
    const int wm = (wid & 1)*32, wn = (wid >> 1)*32;
    const int qr = lane >> 2, qc = lane & 3;

    float acc[2][4][4];
    #pragma unroll
    for (int mi = 0; mi < 2; mi++)
        #pragma unroll
        for (int ni = 0; ni < 4; ni++)
            #pragma unroll
            for (int r = 0; r < 4; r++) acc[mi][ni][r] = 0.f;

    const float* inb = in + (size_t)b*CIN*L;

    for (int ci0 = 0; ci0 < CIN; ci0 += 16){
        for (int idx = tid; idx < 16*LWD; idx += 256){
            int r = idx / LWD, c = idx - r*LWD;
            int l = l0 + c - PAD;
            xs[r][c] = (l >= 0 && l < L) ? inb[(size_t)(ci0 + r)*L + l] : 0.f;
        }
        for (int idx = tid; idx < 64*KCH; idx += 256){
            int c = idx / KCH, i = idx - c*KCH;
            ws[c][i] = w[((size_t)(co0 + c)*CIN + ci0)*TAPS + i];
        }
        __syncthreads();
        #pragma unroll
        for (int tap = 0; tap < TAPS; tap++){
            #pragma unroll
            for (int ks = 0; ks < 2; ks++){
                uint32_t A[2][4], B[4][2];
                const int k0 = ks*8 + qc;
                #pragma unroll
                for (int mi = 0; mi < 2; mi++){
                    int m = wm + mi*16 + qr;
                    A[mi][0] = f2tf32(ws[m    ][ k0     *TAPS + tap]);
                    A[mi][1] = f2tf32(ws[m + 8][ k0     *TAPS + tap]);
                    A[mi][2] = f2tf32(ws[m    ][(k0 + 4)*TAPS + tap]);
                    A[mi][3] = f2tf32(ws[m + 8][(k0 + 4)*TAPS + tap]);
                }
                #pragma unroll
                for (int ni = 0; ni < 4; ni++){
                    int n = wn + ni*8 + qr + tap;
                    B[ni][0] = f2tf32(xs[k0    ][n]);
                    B[ni][1] = f2tf32(xs[k0 + 4][n]);
                }
                #pragma unroll
                for (int mi = 0; mi < 2; mi++)
                    #pragma unroll
                    for (int ni = 0; ni < 4; ni++)
                        mma_tf32(acc[mi][ni], A[mi], B[ni]);
            }
        }
        __syncthreads();
    }

    #pragma unroll
    for (int mi = 0; mi < 2; mi++){
        int r0 = co0 + wm + mi*16 + qr;
        float b0 = bias[r0], b1 = bias[r0 + 8];
        #pragma unroll
        for (int ni = 0; ni < 4; ni++){
            int c0 = l0 + wn + ni*8 + 2*qc;
            float* C = acc[mi][ni];
            if (((L & 1) == 0) && (c0 + 1) < L){
                *(float2*)&out[((size_t)b*COUT + r0    )*L + c0] = make_float2(C[0] + b0, C[1] + b0);
                *(float2*)&out[((size_t)b*COUT + r0 + 8)*L + c0] = make_float2(C[2] + b1, C[3] + b1);
            } else {
                if (c0 < L){
                    out[((size_t)b*COUT + r0    )*L + c0] = C[0] + b0;
                    out[((size_t)b*COUT + r0 + 8)*L + c0] = C[2] + b1;
                }
                if (c0 + 1 < L){
                    out[((size_t)b*COUT + r0    )*L + c0 + 1] = C[1] + b0;
                    out[((size_t)b*COUT + r0 + 8)*L + c0 + 1] = C[3] + b1;
                }
            }
        }
    }
}

// ---------------- GN0 + FiLM + mish -----------------------------------------
__global__ void k_gn0(const float* __restrict__ in, const float* __restrict__ gg,
                      const float* __restrict__ gb, float* __restrict__ out){
    __shared__ float tile[64][32];
    __shared__ float rs[8][32], rq[8][32];
    __shared__ float cm[32], cr[32];
    int l0 = blockIdx.x*32, g = blockIdx.y, b = blockIdx.z;
    int tid = threadIdx.x, col = tid & 31, seg = tid >> 5;
    size_t base = ((size_t)(b*512 + g*64))*512 + l0;
    #pragma unroll
    for (int k = 0; k < 8; k++){
        int idx = k*256 + tid; int r = idx >> 5, c = idx & 31;
        tile[r][c] = in[base + (size_t)r*512 + c];
    }
    __syncthreads();
    float s = 0.f, q = 0.f;
    #pragma unroll
    for (int r = 0; r < 8; r++){ float v = tile[seg*8 + r][col]; s += v; q += v*v; }
    rs[seg][col] = s; rq[seg][col] = q;
    __syncthreads();
    if (tid < 32){
        float S = 0.f, Q = 0.f;
        #pragma unroll
        for (int w = 0; w < 8; w++){ S += rs[w][tid]; Q += rq[w][tid]; }
        float m = S * (1.f/64.f); float var = Q * (1.f/64.f) - m*m;
        cm[tid] = m; cr[tid] = rsqrtf(var + EPSV);
    }
    __syncthreads();
    #pragma unroll
    for (int k = 0; k < 8; k++){
        int idx = k*256 + tid; int r = idx >> 5, c = idx & 31;
        int ch = g*64 + r;
        float v = (tile[r][c] - cm[c]) * cr[c] * gg[ch] + gb[ch];
        float sc = g_ss[b*1024 + ch], sh = g_ss[b*1024 + 512 + ch];
        v = v * (1.f + sc) + sh;
        out[base + (size_t)r*512 + c] = mishf(v);
    }
}

// ---------------- GN1 + mish + residual add (in-place on d_out) -------------
__global__ void k_gn1(const float* __restrict__ in, const float* __restrict__ gg,
                      const float* __restrict__ gb, float* __restrict__ dout){
    __shared__ float tile[64][32];
    __shared__ float rs[8][32], rq[8][32];
    __shared__ float cm[32], cr[32];
    int l0 = blockIdx.x*32, g = blockIdx.y, b = blockIdx.z;
    int tid = threadIdx.x, col = tid & 31, seg = tid >> 5;
    size_t base = ((size_t)(b*512 + g*64))*512 + l0;
    #pragma unroll
    for (int k = 0; k < 8; k++){
        int idx = k*256 + tid; int r = idx >> 5, c = idx & 31;
        tile[r][c] = in[base + (size_t)r*512 + c];
    }
    __syncthreads();
    float s = 0.f, q = 0.f;
    #pragma unroll
    for (int r = 0; r < 8; r++){ float v = tile[seg*8 + r][col]; s += v; q += v*v; }
    rs[seg][col] = s; rq[seg][col] = q;
    __syncthreads();
    if (tid < 32){
        float S = 0.f, Q = 0.f;
        #pragma unroll
        for (int w = 0; w < 8; w++){ S += rs[w][tid]; Q += rq[w][tid]; }
        float m = S * (1.f/64.f); float var = Q * (1.f/64.f) - m*m;
        cm[tid] = m; cr[tid] = rsqrtf(var + EPSV);
    }
    __syncthreads();
    #pragma unroll
    for (int k = 0; k < 8; k++){
        int idx = k*256 + tid; int r = idx >> 5, c = idx & 31;
        int ch = g*64 + r;
        float v = (tile[r][c] - cm[c]) * cr[c] * gg[ch] + gb[ch];
        size_t o = base + (size_t)r*512 + c;
        dout[o] = mishf(v) + dout[o];
    }
}

// ---------------- LN over channels of out[cidx[b]] -> g_xln (b,c,t) ---------
__global__ void k_xln(const float* __restrict__ out, const float* __restrict__ gg,
                      const float* __restrict__ gb, const int* __restrict__ cidx){
    int b = blockIdx.y;
    int t = blockIdx.x*128 + threadIdx.x;
    int bi = cidx[b];
    const float* src = out + (size_t)bi*512*512 + t;
    float s = 0.f, q = 0.f;
    for (int c = 0; c < 512; c++){ float v = src[(size_t)c*512]; s += v; q += v*v; }
    float m = s * (1.f/512.f);
    float r = rsqrtf(q * (1.f/512.f) - m*m + EPSV);
    float* dst = g_xln + (size_t)b*512*512 + t;
    for (int c = 0; c < 512; c++){
        float v = src[(size_t)c*512];
        dst[(size_t)c*512] = (v - m) * r * gg[c] + gb[c];
    }
}

// ---------------- LN(cond[cidx[b]]) -> g_cn (b, 768, 77) transposed ---------
__global__ void k_cn(const float* __restrict__ cond, const float* __restrict__ gg,
                     const float* __restrict__ gb, const int* __restrict__ cidx){
    __shared__ float row[768];
    __shared__ float wsum[8], wsq[8];
    int n = blockIdx.x, b = blockIdx.y;
    int bi = cidx[b];
    int tid = threadIdx.x, lane = tid & 31, w = tid >> 5;
    const float* src = cond + ((size_t)bi*77 + n)*768;
    float s = 0.f, q = 0.f;
    for (int i = tid; i < 768; i += 256){ float v = src[i]; row[i] = v; s += v; q += v*v; }
    #pragma unroll
    for (int o = 16; o; o >>= 1){ s += __shfl_xor_sync(0xffffffffu, s, o); q += __shfl_xor_sync(0xffffffffu, q, o); }
    if (lane == 0){ wsum[w] = s; wsq[w] = q; }
    __syncthreads();
    if (tid == 0){
        float S = 0.f, Q = 0.f;
        #pragma unroll
        for (int i = 0; i < 8; i++){ S += wsum[i]; Q += wsq[i]; }
        float m = S * (1.f/768.f); float var = Q * (1.f/768.f) - m*m;
        wsum[0] = m; wsq[0] = rsqrtf(var + EPSV);
    }
    __syncthreads();
    float m = wsum[0], r = wsq[0];
    for (int i = tid; i < 768; i += 256)
        g_cn[((size_t)b*768 + i)*77 + n] = (row[i] - m) * r * gg[i] + gb[i];
}

// ---------------- q softmax over head-dim (64 rows) at fixed (b,t) ----------
__global__ void k_qsm(float* __restrict__ q){
    __shared__ float tile[64][32];
    __shared__ float red[8][32];
    __shared__ float colm[32], cols[32];
    int t0 = blockIdx.x*32, h = blockIdx.y, b = blockIdx.z;
    int tid = threadIdx.x, col = tid & 31, seg = tid >> 5;
    size_t base = ((size_t)(b*512 + h*64))*512 + t0;
    #pragma unroll
    for (int k = 0; k < 8; k++){
        int idx = k*256 + tid; int r = idx >> 5, c = idx & 31;
        tile[r][c] = q[base + (size_t)r*512 + c];
    }
    __syncthreads();
    float m = -1e30f;
    #pragma unroll
    for (int r = 0; r < 8; r++) m = fmaxf(m, tile[seg*8 + r][col]);
    red[seg][col] = m;
    __syncthreads();
    if (tid < 32){
        float mm = red[0][tid];
        #pragma unroll
        for (int w = 1; w < 8; w++) mm = fmaxf(mm, red[w][tid]);
        colm[tid] = mm;
    }
    __syncthreads();
    float s = 0.f;
    #pragma unroll
    for (int r = 0; r < 8; r++) s += expf(tile[seg*8 + r][col] - colm[col]);
    red[seg][col] = s;
    __syncthreads();
    if (tid < 32){
        float ss2 = 0.f;
        #pragma unroll
        for (int w = 0; w < 8; w++) ss2 += red[w][tid];
        cols[tid] = 1.f / ss2;
    }
    __syncthreads();
    #pragma unroll
    for (int k = 0; k < 8; k++){
        int idx = k*256 + tid; int r = idx >> 5, c = idx & 31;
        q[base + (size_t)r*512 + c] = expf(tile[r][c] - colm[c]) * cols[c];
    }
}

// ---------------- k softmax over n (77) at fixed (b,d) ----------------------
__global__ void k_ksm(float* __restrict__ kbuf){
    int b = blockIdx.x;
    int d = blockIdx.y*8 + (threadIdx.x >> 5);
    int lane = threadIdx.x & 31;
    float* row = kbuf + ((size_t)b*512 + d)*77;
    float v0 = row[lane];
    float v1 = row[lane + 32];
    bool has2 = (lane + 64) < 77;
    float v2 = has2 ? row[lane + 64] : -1e30f;
    float m = fmaxf(fmaxf(v0, v1), v2);
    #pragma unroll
    for (int o = 16; o; o >>= 1) m = fmaxf(m, __shfl_xor_sync(0xffffffffu, m, o));
    float e0 = expf(v0 - m), e1 = expf(v1 - m), e2 = has2 ? expf(v2 - m) : 0.f;
    float s = e0 + e1 + e2;
    #pragma unroll
    for (int o = 16; o; o >>= 1) s += __shfl_xor_sync(0xffffffffu, s, o);
    float inv = 1.f / s;
    row[lane] = e0 * inv;
    row[lane + 32] = e1 * inv;
    if (has2) row[lane + 64] = e2 * inv;
}

// ---------------- attn[b,h,d,l] = sum_n k[b,hd+d,n] * v[b,hd+l,n] ------------
__global__ void k_attn(const float* __restrict__ kbuf, const float* __restrict__ vbuf){
    __shared__ float ks[64][80], vs[64][80];
    int h = blockIdx.x, b = blockIdx.y;
    int tid = threadIdx.x, tx = tid & 15, ty = tid >> 4;
    const float* kp = kbuf + ((size_t)(b*512 + h*64))*77;
    const float* vp = vbuf + ((size_t)(b*512 + h*64))*77;
    for (int idx = tid; idx < 64*80; idx += 256){
        int r = idx / 80, c = idx - r*80;
        float kv = (c < 77) ? kp[(size_t)r*77 + c] : 0.f;
        float vv = (c < 77) ? vp[(size_t)r*77 + c] : 0.f;
        ks[r][c] = kv; vs[r][c] = vv;
    }
    __syncthreads();
    float acc[4][4];
    #pragma unroll
    for (int i = 0; i < 4; i++)
        #pragma unroll
        for (int j = 0; j < 4; j++) acc[i][j] = 0.f;
    for (int n = 0; n < 77; n++){
        float a[4], c4[4];
        #pragma unroll
        for (int i = 0; i < 4; i++) a[i] = ks[ty*4 + i][n];
        #pragma unroll
        for (int j = 0; j < 4; j++) c4[j] = vs[tx*4 + j][n];
        #pragma unroll
        for (int i = 0; i < 4; i++)
            #pragma unroll
            for (int j = 0; j < 4; j++) acc[i][j] = fmaf(a[i], c4[j], acc[i][j]);
    }
    #pragma unroll
    for (int i = 0; i < 4; i++)
        #pragma unroll
        for (int j = 0; j < 4; j++)
            g_attn[(((size_t)(b*8 + h))*64 + ty*4 + i)*64 + tx*4 + j] = acc[i][j];
}

// ---------------- y = q @ attn, scatter-add into d_out ----------------------
__global__ void k_y(const float* __restrict__ q, float* __restrict__ out,
                    const int* __restrict__ cidx){
    __shared__ __align__(16) float qs[64][128];
    __shared__ float as[64][64];
    int t0 = blockIdx.x*128, h = blockIdx.y, b = blockIdx.z;
    int bi = cidx[b];
    int tid = threadIdx.x, tx = tid & 15, ty = tid >> 4;
    for (int idx = tid; idx < 64*128; idx += 256){
        int r = idx >> 7, c = idx & 127;
        qs[r][c] = q[((size_t)(b*512 + h*64 + r))*512 + t0 + c];
    }
    for (int idx = tid; idx < 64*64; idx += 256){
        int r = idx >> 6, c = idx & 63;
        as[r][c] = g_attn[(((size_t)(b*8 + h))*64 + r)*64 + c];
    }
    __syncthreads();
    float acc[4][8];
    #pragma unroll
    for (int i = 0; i < 4; i++)
        #pragma unroll
        for (int j = 0; j < 8; j++) acc[i][j] = 0.f;
    for (int d = 0; d < 64; d++){
        float4 q0 = *reinterpret_cast<const float4*>(&qs[d][tx*8]);
        float4 q1 = *reinterpret_cast<const float4*>(&qs[d][tx*8 + 4]);
        float qr[8] = {q0.x,q0.y,q0.z,q0.w,q1.x,q1.y,q1.z,q1.w};
        float ar[4];
        #pragma unroll
        for (int i = 0; i < 4; i++) ar[i] = as[d][ty*4 + i];
        #pragma unroll
        for (int i = 0; i < 4; i++)
            #pragma unroll
            for (int j = 0; j < 8; j++) acc[i][j] = fmaf(ar[i], qr[j], acc[i][j]);
    }
    #pragma unroll
    for (int i = 0; i < 4; i++){
        int ch = h*64 + ty*4 + i;
        #pragma unroll
        for (int j = 0; j < 8; j++){
            atomicAdd(&out[((size_t)bi*512 + ch)*512 + t0 + tx*8 + j], acc[i][j]);
        }
    }
}

// ---------------- launch ----------------------------------------------------
extern "C" void kernel_launch(void* const* d_in, const int* in_sizes, int n_in,
                              void* d_out, int out_size){
    const float* x       = (const float*)d_in[0];
    const float* t       = (const float*)d_in[1];
    const float* cond    = (const float*)d_in[2];
    const float* conv0_w = (const float*)d_in[3];
    const float* conv0_b = (const float*)d_in[4];
    const float* gn0_g   = (const float*)d_in[5];
    const float* gn0_b   = (const float*)d_in[6];
    const float* tm_w    = (const float*)d_in[7];
    const float* tm_b    = (const float*)d_in[8];
    const float* conv1_w = (const float*)d_in[9];
    const float* conv1_b = (const float*)d_in[10];
    const float* gn1_g   = (const float*)d_in[11];
    const float* gn1_b   = (const float*)d_in[12];
    const float* res_w   = (const float*)d_in[13];
    const float* res_b   = (const float*)d_in[14];
    const float* ln_x_g  = (const float*)d_in[15];
    const float* ln_x_b  = (const float*)d_in[16];
    const float* ln_c_g  = (const float*)d_in[17];
    const float* ln_c_b  = (const float*)d_in[18];
    const float* q_w     = (const float*)d_in[19];
    const float* q_b     = (const float*)d_in[20];
    const float* k_w     = (const float*)d_in[21];
    const float* k_b     = (const float*)d_in[22];
    const float* v_w     = (const float*)d_in[23];
    const float* v_b     = (const float*)d_in[24];
    const int*   cidx    = (const int*)d_in[25];
    float* out = (float*)d_out;

    float *p_h, *p_h2, *p_xln, *p_q, *p_cn, *p_k, *p_v;
    cudaGetSymbolAddress((void**)&p_h,   g_h);
    cudaGetSymbolAddress((void**)&p_h2,  g_h2);
    cudaGetSymbolAddress((void**)&p_xln, g_xln);
    cudaGetSymbolAddress((void**)&p_q,   g_q);
    cudaGetSymbolAddress((void**)&p_cn,  g_cn);
    cudaGetSymbolAddress((void**)&p_k,   g_k);
    cudaGetSymbolAddress((void**)&p_v,   g_v);

    // FiLM scale/shift
    k_ss<<<64, 256>>>(t, tm_w, tm_b);
    // conv0 -> g_h
    k_conv<256,5,2><<<dim3(4,8,64), 256>>>(x, conv0_w, conv0_b, p_h, 512);
    // gn0 + FiLM + mish -> g_h2
    k_gn0<<<dim3(16,8,64), 256>>>(p_h, gn0_g, gn0_b, p_h2);
    // conv1 -> g_h
    k_conv<512,5,2><<<dim3(4,8,64), 256>>>(p_h2, conv1_w, conv1_b, p_h, 512);
    // residual 1x1 conv -> d_out
    k_conv<256,1,0><<<dim3(4,8,64), 256>>>(x, res_w, res_b, out, 512);
    // out = mish(gn1(conv1)) + res  (in-place on d_out)
    k_gn1<<<dim3(16,8,64), 256>>>(p_h, gn1_g, gn1_b, out);
    // LN over channels of out[cidx] -> g_xln (b,c,t)
    k_xln<<<dim3(4,64), 128>>>(out, ln_x_g, ln_x_b, cidx);
    // q projection (1x1 conv) -> g_q (b,d,t)
    k_conv<512,1,0><<<dim3(4,8,64), 256>>>(p_xln, q_w, q_b, p_q, 512);
    // q softmax over head-dim
    k_qsm<<<dim3(16,8,64), 256>>>(p_q);
    // LN(cond[cidx]) -> g_cn (b, 768, 77)
    k_cn<<<dim3(77,64), 256>>>(cond, ln_c_g, ln_c_b, cidx);
    // k,v projections (1x1 conv over 768 ch, L=77)
    k_conv<768,1,0><<<dim3(1,8,64), 256>>>(p_cn, k_w, k_b, p_k, 77);
    k_conv<768,1,0><<<dim3(1,8,64), 256>>>(p_cn, v_w, v_b, p_v, 77);
    // k softmax over n
    k_ksm<<<dim3(64,64), 256>>>(p_k);
    // attn = k^T v per (b,h)
    k_attn<<<dim3(8,64), 256>>>(p_k, p_v);
    // y = q @ attn, scatter-add into d_out
    k_y<<<dim3(4,8,64), 256>>>(p_q, out, cidx);
}

// round 4
// speedup vs baseline: 1.9203x; 1.0124x over previous
#include <cuda_runtime.h>
#include <math.h>
#include <stdint.h>

#define EPSV 1e-5f

// ---------------- scratch (allocation-free: device globals) ----------------
__device__ float g_ss  [64*1024];
__device__ float g_h2  [64*512*512];
__device__ float g_xln [64*512*512];
__device__ float g_q   [64*512*512];
__device__ float g_cn  [64*768*77];
__device__ float g_k   [64*512*77];
__device__ float g_v   [64*512*77];
__device__ float g_attn[64*8*64*64];

// fast mish: x * tanh(softplus(x)) ; tanh(log u) = (u^2-1)/(u^2+1), u = 1+e^x
__device__ __forceinline__ float mishf(float x){
    float xc = fminf(x, 15.f);
    float e  = __expf(xc);
    float u  = 1.f + e;
    float u2 = u * u;
    return x * __fdividef(u2 - 1.f, u2 + 1.f);
}

// ---------------- tf32 mma helpers ------------------------------------------
__device__ __forceinline__ uint32_t f2tf32(float f){
    uint32_t r; asm("cvt.rna.tf32.f32 %0, %1;" : "=r"(r) : "f"(f)); return r;
}
__device__ __forceinline__ void mma_tf32(float* c, const uint32_t* a, const uint32_t* b){
    asm("mma.sync.aligned.m16n8k8.row.col.f32.tf32.tf32.f32 "
        "{%0,%1,%2,%3}, {%4,%5,%6,%7}, {%8,%9}, {%0,%1,%2,%3};"
        : "+f"(c[0]), "+f"(c[1]), "+f"(c[2]), "+f"(c[3])
        : "r"(a[0]), "r"(a[1]), "r"(a[2]), "r"(a[3]), "r"(b[0]), "r"(b[1]));
}

// ---------------- ss = mish(t) @ tm_w^T + tm_b -----------------------------
__global__ void k_ss(const float* __restrict__ t, const float* __restrict__ w,
                     const float* __restrict__ bias){
    __shared__ float tm[512];
    int b = blockIdx.x, tid = threadIdx.x;
    for (int i = tid; i < 512; i += 256) tm[i] = mishf(t[b*512 + i]);
    __syncthreads();
    for (int o = tid; o < 1024; o += 256){
        const float* wr = w + (size_t)o * 512;
        float acc = bias[o];
        #pragma unroll 8
        for (int i = 0; i < 512; i++) acc = fmaf(tm[i], wr[i], acc);
        g_ss[b*1024 + o] = acc;
    }
}

// ---------------- conv1d as implicit GEMM on tf32 tensor cores --------------
// MODE 0: plain (bias, guarded stores; used for res conv + k/v proj)
// MODE 1: + GroupNorm + FiLM + mish                (conv0)
// MODE 2: + GroupNorm + mish + residual add into out (conv1)
// MODE 3: + softmax over the 64 rows (head dim)     (q proj)
// Block: 256 thr = 8 warps (2m x 4n). Block tile M=64(co) x N=128(l).
template<int CIN, int TAPS, int PAD, int MODE>
__global__ void k_conv(const float* __restrict__ in, const float* __restrict__ w,
                       const float* __restrict__ bias, float* __restrict__ out, int L,
                       const float* __restrict__ gg, const float* __restrict__ gb){
    constexpr int LWD = 128 + TAPS - 1;   // valid data columns in xs
    constexpr int LWS = 136;              // padded row stride
    constexpr int KCH = 16*TAPS;          // weights per co per chunk
    constexpr int WST = KCH + 4;          // ws row stride
    constexpr int EST = 132;              // epilogue tile row stride
    constexpr int CNT1 = 16*LWS + 64*WST;
    constexpr int CNT2 = (MODE ? 64*EST : 0);
    constexpr int CNT  = CNT1 > CNT2 ? CNT1 : CNT2;
    __shared__ __align__(16) uint32_t sm[CNT];
    __shared__ float red0[256], red1[256];
    __shared__ float stA[128], stB[128];
    __shared__ float rg[64], rb[64], rsc[64], rsh[64];
    uint32_t (*xs)[LWS] = (uint32_t(*)[LWS])sm;
    uint32_t (*ws)[WST] = (uint32_t(*)[WST])(sm + 16*LWS);

    const int l0 = blockIdx.x*128, co0 = blockIdx.y*64, b = blockIdx.z;
    const int COUT = gridDim.y*64;
    const int tid = threadIdx.x, lane = tid & 31, wid = tid >> 5;
    const int wm = (wid & 1)*32, wn = (wid >> 1)*32;
    const int qr = lane >> 2, qc = lane & 3;

    float acc[2][4][4];
    #pragma unroll
    for (int mi = 0; mi < 2; mi++)
        #pragma unroll
        for (int ni = 0; ni < 4; ni++)
            #pragma unroll
            for (int r = 0; r < 4; r++) acc[mi][ni][r] = 0.f;

    const float* inb = in + (size_t)b*CIN*L;

    for (int ci0 = 0; ci0 < CIN; ci0 += 16){
        for (int idx = tid; idx < 16*LWD; idx += 256){
            int r = idx / LWD, c = idx - r*LWD;
            int l = l0 + c - PAD;
            xs[r][c] = f2tf32((l >= 0 && l < L) ? inb[(size_t)(ci0 + r)*L + l] : 0.f);
        }
        for (int idx = tid; idx < 64*KCH; idx += 256){
            int c = idx / KCH, i = idx - c*KCH;
            ws[c][i] = f2tf32(w[((size_t)(co0 + c)*CIN + ci0)*TAPS + i]);
        }
        __syncthreads();
        #pragma unroll
        for (int tap = 0; tap < TAPS; tap++){
            #pragma unroll
            for (int ks = 0; ks < 2; ks++){
                uint32_t A[2][4], B[4][2];
                const int k0 = ks*8 + qc;
                #pragma unroll
                for (int mi = 0; mi < 2; mi++){
                    int m = wm + mi*16 + qr;
                    A[mi][0] = ws[m    ][ k0     *TAPS + tap];
                    A[mi][1] = ws[m + 8][ k0     *TAPS + tap];
                    A[mi][2] = ws[m    ][(k0 + 4)*TAPS + tap];
                    A[mi][3] = ws[m + 8][(k0 + 4)*TAPS + tap];
                }
                #pragma unroll
                for (int ni = 0; ni < 4; ni++){
                    int n = wn + ni*8 + qr + tap;
                    B[ni][0] = xs[k0    ][n];
                    B[ni][1] = xs[k0 + 4][n];
                }
                #pragma unroll
                for (int mi = 0; mi < 2; mi++)
                    #pragma unroll
                    for (int ni = 0; ni < 4; ni++)
                        mma_tf32(acc[mi][ni], A[mi], B[ni]);
            }
        }
        __syncthreads();
    }

    if (MODE == 0){
        #pragma unroll
        for (int mi = 0; mi < 2; mi++){
            int r0 = co0 + wm + mi*16 + qr;
            float b0 = bias[r0], b1 = bias[r0 + 8];
            #pragma unroll
            for (int ni = 0; ni < 4; ni++){
                int c0 = l0 + wn + ni*8 + 2*qc;
                float* C = acc[mi][ni];
                if (((L & 1) == 0) && (c0 + 1) < L){
                    *(float2*)&out[((size_t)b*COUT + r0    )*L + c0] = make_float2(C[0]+b0, C[1]+b0);
                    *(float2*)&out[((size_t)b*COUT + r0 + 8)*L + c0] = make_float2(C[2]+b1, C[3]+b1);
                } else {
                    if (c0 < L){
                        out[((size_t)b*COUT + r0    )*L + c0] = C[0] + b0;
                        out[((size_t)b*COUT + r0 + 8)*L + c0] = C[2] + b1;
                    }
                    if (c0 + 1 < L){
                        out[((size_t)b*COUT + r0    )*L + c0 + 1] = C[1] + b0;
                        out[((size_t)b*COUT + r0 + 8)*L + c0 + 1] = C[3] + b1;
                    }
                }
            }
        }
        return;
    }

    // ---- fused epilogue (full 64x128 tile; L == 512 guaranteed here) ----
    float* et = (float*)sm;
    #pragma unroll
    for (int mi = 0; mi < 2; mi++){
        int r0 = wm + mi*16 + qr;
        float b0 = bias[co0 + r0], b1 = bias[co0 + r0 + 8];
        #pragma unroll
        for (int ni = 0; ni < 4; ni++){
            int c0 = wn + ni*8 + 2*qc;
            float* C = acc[mi][ni];
            *(float2*)&et[ r0     *EST + c0] = make_float2(C[0]+b0, C[1]+b0);
            *(float2*)&et[(r0 + 8)*EST + c0] = make_float2(C[2]+b1, C[3]+b1);
        }
    }
    if (MODE == 1 && tid < 64){
        rg[tid]  = gg[co0 + tid];           rb[tid]  = gb[co0 + tid];
        rsc[tid] = g_ss[b*1024 + co0 + tid]; rsh[tid] = g_ss[b*1024 + 512 + co0 + tid];
    }
    if (MODE == 2 && tid < 64){
        rg[tid] = gg[co0 + tid]; rb[tid] = gb[co0 + tid];
    }
    __syncthreads();

    const int c = tid & 127, half = tid >> 7;
    if (MODE == 1 || MODE == 2){
        float s = 0.f, q = 0.f;
        #pragma unroll
        for (int r = 0; r < 32; r++){
            float v = et[(half*32 + r)*EST + c];
            s += v; q += v*v;
        }
        red0[tid] = s; red1[tid] = q;
        __syncthreads();
        if (tid < 128){
            float S = red0[tid] + red0[tid + 128];
            float Q = red1[tid] + red1[tid + 128];
            float m = S * (1.f/64.f);
            stA[tid] = m;
            stB[tid] = rsqrtf(Q * (1.f/64.f) - m*m + EPSV);
        }
        __syncthreads();
    } else { // MODE == 3: softmax over 64 rows per column
        float m = -1e30f;
        #pragma unroll
        for (int r = 0; r < 32; r++) m = fmaxf(m, et[(half*32 + r)*EST + c]);
        red0[tid] = m;
        __syncthreads();
        if (tid < 128) stA[tid] = fmaxf(red0[tid], red0[tid + 128]);
        __syncthreads();
        float s = 0.f;
        #pragma unroll
        for (int r = 0; r < 32; r++) s += __expf(et[(half*32 + r)*EST + c] - stA[c]);
        red1[tid] = s;
        __syncthreads();
        if (tid < 128) stB[tid] = 1.f / (red1[tid] + red1[tid + 128]);
        __syncthreads();
    }

    #pragma unroll 4
    for (int k = 0; k < 32; k++){
        int idx = k*256 + tid;
        int r = idx >> 7, cc = idx & 127;
        float v = et[r*EST + cc];
        size_t gidx = ((size_t)b*COUT + co0 + r)*L + l0 + cc;
        if (MODE == 1){
            v = (v - stA[cc]) * stB[cc] * rg[r] + rb[r];
            v = v * (1.f + rsc[r]) + rsh[r];
            v = mishf(v);
        } else if (MODE == 2){
            v = (v - stA[cc]) * stB[cc] * rg[r] + rb[r];
            v = mishf(v) + out[gidx];
        } else { // MODE == 3
            v = __expf(v - stA[cc]) * stB[cc];
        }
        out[gidx] = v;
    }
}

// ---------------- LN over channels of out[cidx[b]] -> g_xln (b,c,t) ---------
__global__ void k_xln(const float* __restrict__ out, const float* __restrict__ gg,
                      const float* __restrict__ gb, const int* __restrict__ cidx){
    int b = blockIdx.y;
    int t = blockIdx.x*128 + threadIdx.x;
    int bi = cidx[b];
    const float* src = out + (size_t)bi*512*512 + t;
    float s = 0.f, q = 0.f;
    for (int c = 0; c < 512; c++){ float v = src[(size_t)c*512]; s += v; q += v*v; }
    float m = s * (1.f/512.f);
    float r = rsqrtf(q * (1.f/512.f) - m*m + EPSV);
    float* dst = g_xln + (size_t)b*512*512 + t;
    for (int c = 0; c < 512; c++){
        float v = src[(size_t)c*512];
        dst[(size_t)c*512] = (v - m) * r * gg[c] + gb[c];
    }
}

// ---------------- LN(cond[cidx[b]]) -> g_cn (b, 768, 77) transposed ---------
__global__ void k_cn(const float* __restrict__ cond, const float* __restrict__ gg,
                     const float* __restrict__ gb, const int* __restrict__ cidx){
    __shared__ float row[768];
    __shared__ float wsum[8], wsq[8];
    int n = blockIdx.x, b = blockIdx.y;
    int bi = cidx[b];
    int tid = threadIdx.x, lane = tid & 31, w = tid >> 5;
    const float* src = cond + ((size_t)bi*77 + n)*768;
    float s = 0.f, q = 0.f;
    for (int i = tid; i < 768; i += 256){ float v = src[i]; row[i] = v; s += v; q += v*v; }
    #pragma unroll
    for (int o = 16; o; o >>= 1){ s += __shfl_xor_sync(0xffffffffu, s, o); q += __shfl_xor_sync(0xffffffffu, q, o); }
    if (lane == 0){ wsum[w] = s; wsq[w] = q; }
    __syncthreads();
    if (tid == 0){
        float S = 0.f, Q = 0.f;
        #pragma unroll
        for (int i = 0; i < 8; i++){ S += wsum[i]; Q += wsq[i]; }
        float m = S * (1.f/768.f); float var = Q * (1.f/768.f) - m*m;
        wsum[0] = m; wsq[0] = rsqrtf(var + EPSV);
    }
    __syncthreads();
    float m = wsum[0], r = wsq[0];
    for (int i = tid; i < 768; i += 256)
        g_cn[((size_t)b*768 + i)*77 + n] = (row[i] - m) * r * gg[i] + gb[i];
}

// ---------------- k softmax over n (77) at fixed (b,d) ----------------------
__global__ void k_ksm(float* __restrict__ kbuf){
    int b = blockIdx.x;
    int d = blockIdx.y*8 + (threadIdx.x >> 5);
    int lane = threadIdx.x & 31;
    float* row = kbuf + ((size_t)b*512 + d)*77;
    float v0 = row[lane];
    float v1 = row[lane + 32];
    bool has2 = (lane + 64) < 77;
    float v2 = has2 ? row[lane + 64] : -1e30f;
    float m = fmaxf(fmaxf(v0, v1), v2);
    #pragma unroll
    for (int o = 16; o; o >>= 1) m = fmaxf(m, __shfl_xor_sync(0xffffffffu, m, o));
    float e0 = __expf(v0 - m), e1 = __expf(v1 - m), e2 = has2 ? __expf(v2 - m) : 0.f;
    float s = e0 + e1 + e2;
    #pragma unroll
    for (int o = 16; o; o >>= 1) s += __shfl_xor_sync(0xffffffffu, s, o);
    float inv = 1.f / s;
    row[lane] = e0 * inv;
    row[lane + 32] = e1 * inv;
    if (has2) row[lane + 64] = e2 * inv;
}

// ---------------- attn[b,h,d,l] = sum_n k[b,hd+d,n] * v[b,hd+l,n] ------------
__global__ void k_attn(const float* __restrict__ kbuf, const float* __restrict__ vbuf){
    __shared__ float ks[64][80], vs[64][80];
    int h = blockIdx.x, b = blockIdx.y;
    int tid = threadIdx.x, tx = tid & 15, ty = tid >> 4;
    const float* kp = kbuf + ((size_t)(b*512 + h*64))*77;
    const float* vp = vbuf + ((size_t)(b*512 + h*64))*77;
    for (int idx = tid; idx < 64*80; idx += 256){
        int r = idx / 80, c = idx - r*80;
        float kv = (c < 77) ? kp[(size_t)r*77 + c] : 0.f;
        float vv = (c < 77) ? vp[(size_t)r*77 + c] : 0.f;
        ks[r][c] = kv; vs[r][c] = vv;
    }
    __syncthreads();
    float acc[4][4];
    #pragma unroll
    for (int i = 0; i < 4; i++)
        #pragma unroll
        for (int j = 0; j < 4; j++) acc[i][j] = 0.f;
    for (int n = 0; n < 77; n++){
        float a[4], c4[4];
        #pragma unroll
        for (int i = 0; i < 4; i++) a[i] = ks[ty*4 + i][n];
        #pragma unroll
        for (int j = 0; j < 4; j++) c4[j] = vs[tx*4 + j][n];
        #pragma unroll
        for (int i = 0; i < 4; i++)
            #pragma unroll
            for (int j = 0; j < 4; j++) acc[i][j] = fmaf(a[i], c4[j], acc[i][j]);
    }
    #pragma unroll
    for (int i = 0; i < 4; i++)
        #pragma unroll
        for (int j = 0; j < 4; j++)
            g_attn[(((size_t)(b*8 + h))*64 + ty*4 + i)*64 + tx*4 + j] = acc[i][j];
}

// ---------------- y = q @ attn, scatter-add into d_out ----------------------
__global__ void k_y(const float* __restrict__ q, float* __restrict__ out,
                    const int* __restrict__ cidx){
    __shared__ __align__(16) float qs[64][128];
    __shared__ float as[64][64];
    int t0 = blockIdx.x*128, h = blockIdx.y, b = blockIdx.z;
    int bi = cidx[b];
    int tid = threadIdx.x, tx = tid & 15, ty = tid >> 4;
    for (int idx = tid; idx < 64*128; idx += 256){
        int r = idx >> 7, c = idx & 127;
        qs[r][c] = q[((size_t)(b*512 + h*64 + r))*512 + t0 + c];
    }
    for (int idx = tid; idx < 64*64; idx += 256){
        int r = idx >> 6, c = idx & 63;
        as[r][c] = g_attn[(((size_t)(b*8 + h))*64 + r)*64 + c];
    }
    __syncthreads();
    float acc[4][8];
    #pragma unroll
    for (int i = 0; i < 4; i++)
        #pragma unroll
        for (int j = 0; j < 8; j++) acc[i][j] = 0.f;
    for (int d = 0; d < 64; d++){
        float4 q0 = *reinterpret_cast<const float4*>(&qs[d][tx*8]);
        float4 q1 = *reinterpret_cast<const float4*>(&qs[d][tx*8 + 4]);
        float qr[8] = {q0.x,q0.y,q0.z,q0.w,q1.x,q1.y,q1.z,q1.w};
        float ar[4];
        #pragma unroll
        for (int i = 0; i < 4; i++) ar[i] = as[d][ty*4 + i];
        #pragma unroll
        for (int i = 0; i < 4; i++)
            #pragma unroll
            for (int j = 0; j < 8; j++) acc[i][j] = fmaf(ar[i], qr[j], acc[i][j]);
    }
    #pragma unroll
    for (int i = 0; i < 4; i++){
        int ch = h*64 + ty*4 + i;
        #pragma unroll
        for (int j = 0; j < 8; j++){
            atomicAdd(&out[((size_t)bi*512 + ch)*512 + t0 + tx*8 + j], acc[i][j]);
        }
    }
}

// ---------------- launch ----------------------------------------------------
extern "C" void kernel_launch(void* const* d_in, const int* in_sizes, int n_in,
                              void* d_out, int out_size){
    const float* x       = (const float*)d_in[0];
    const float* t       = (const float*)d_in[1];
    const float* cond    = (const float*)d_in[2];
    const float* conv0_w = (const float*)d_in[3];
    const float* conv0_b = (const float*)d_in[4];
    const float* gn0_g   = (const float*)d_in[5];
    const float* gn0_b   = (const float*)d_in[6];
    const float* tm_w    = (const float*)d_in[7];
    const float* tm_b    = (const float*)d_in[8];
    const float* conv1_w = (const float*)d_in[9];
    const float* conv1_b = (const float*)d_in[10];
    const float* gn1_g   = (const float*)d_in[11];
    const float* gn1_b   = (const float*)d_in[12];
    const float* res_w   = (const float*)d_in[13];
    const float* res_b   = (const float*)d_in[14];
    const float* ln_x_g  = (const float*)d_in[15];
    const float* ln_x_b  = (const float*)d_in[16];
    const float* ln_c_g  = (const float*)d_in[17];
    const float* ln_c_b  = (const float*)d_in[18];
    const float* q_w     = (const float*)d_in[19];
    const float* q_b     = (const float*)d_in[20];
    const float* k_w     = (const float*)d_in[21];
    const float* k_b     = (const float*)d_in[22];
    const float* v_w     = (const float*)d_in[23];
    const float* v_b     = (const float*)d_in[24];
    const int*   cidx    = (const int*)d_in[25];
    float* out = (float*)d_out;

    float *p_h2, *p_xln, *p_q, *p_cn, *p_k, *p_v;
    cudaGetSymbolAddress((void**)&p_h2,  g_h2);
    cudaGetSymbolAddress((void**)&p_xln, g_xln);
    cudaGetSymbolAddress((void**)&p_q,   g_q);
    cudaGetSymbolAddress((void**)&p_cn,  g_cn);
    cudaGetSymbolAddress((void**)&p_k,   g_k);
    cudaGetSymbolAddress((void**)&p_v,   g_v);

    // FiLM scale/shift
    k_ss<<<64, 256>>>(t, tm_w, tm_b);
    // residual 1x1 conv -> d_out (must precede fused conv1)
    k_conv<256,1,0,0><<<dim3(4,8,64), 256>>>(x, res_w, res_b, out, 512, nullptr, nullptr);
    // conv0 + GN0 + FiLM + mish -> g_h2
    k_conv<256,5,2,1><<<dim3(4,8,64), 256>>>(x, conv0_w, conv0_b, p_h2, 512, gn0_g, gn0_b);
    // conv1 + GN1 + mish + residual add -> d_out
    k_conv<512,5,2,2><<<dim3(4,8,64), 256>>>(p_h2, conv1_w, conv1_b, out, 512, gn1_g, gn1_b);
    // LN over channels of out[cidx] -> g_xln (b,c,t)
    k_xln<<<dim3(4,64), 128>>>(out, ln_x_g, ln_x_b, cidx);
    // q projection + softmax over head-dim -> g_q
    k_conv<512,1,0,3><<<dim3(4,8,64), 256>>>(p_xln, q_w, q_b, p_q, 512, nullptr, nullptr);
    // LN(cond[cidx]) -> g_cn (b, 768, 77)
    k_cn<<<dim3(77,64), 256>>>(cond, ln_c_g, ln_c_b, cidx);
    // k,v projections (1x1 conv over 768 ch, L=77)
    k_conv<768,1,0,0><<<dim3(1,8,64), 256>>>(p_cn, k_w, k_b, p_k, 77, nullptr, nullptr);
    k_conv<768,1,0,0><<<dim3(1,8,64), 256>>>(p_cn, v_w, v_b, p_v, 77, nullptr, nullptr);
    // k softmax over n
    k_ksm<<<dim3(64,64), 256>>>(p_k);
    // attn = k^T v per (b,h)
    k_attn<<<dim3(8,64), 256>>>(p_k, p_v);
    // y = q @ attn, scatter-add into d_out
    k_y<<<dim3(4,8,64), 256>>>(p_q, out, cidx);
}